// round 12
// baseline (speedup 1.0000x reference)
#include <cuda_runtime.h>
#include <cuda_fp16.h>

#define NN 50000
#define EE 800000
#define ETOT (EE + NN)          // 850000
#define FIN 128
#define HID 32
#define HEADS 4
#define F1 128                  // HEADS*HID
#define OUTC 32
#define CAP 64                  // bucket capacity per node (max degree ~36)

// ---- scratch (no allocs allowed) ----
__device__ __half g_xl1h[NN * F1];      // layer1 transformed features (fp16)
__device__ __align__(16) float g_asrc1[NN * HEADS];
__device__ __align__(16) float g_adst1[NN * HEADS];
__device__ float g_xl2[NN * OUTC];
__device__ float g_asrc2[NN];
__device__ float g_adst2[NN];
__device__ float g_part[512];
__device__ __align__(16) float g_coef1[4];
__device__ float g_coef2;
// bucketed edge store: node d owns slots [d*CAP, d*CAP+cnt[d])
__device__ int  g_cnt[NN];
__device__ __align__(16) int2 g_es2[NN * CAP];   // (src, ea_bits)

#define FMA2(d, a, b) asm("fma.rn.f32x2 %0, %1, %2, %0;" : "+l"(d) : "l"(a), "l"(b))

// ---------------------------------------------------------------------------
// prep: zero g_cnt + easum block partials + coef dots (one kernel)
__global__ void __launch_bounds__(256) k_prep(
    const float* __restrict__ ea,
    const float* __restrict__ l1e, const float* __restrict__ a1e,
    const float* __restrict__ l2e, const float* __restrict__ a2e) {
    int t0 = blockIdx.x * blockDim.x + threadIdx.x;
    int stride = gridDim.x * blockDim.x;   // 512*256 = 131072
    for (int i = t0; i < NN; i += stride) g_cnt[i] = 0;

    float s = 0.f;
    for (int i = t0; i < EE; i += stride) s += ea[i];
    for (int o = 16; o; o >>= 1) s += __shfl_xor_sync(0xffffffffu, s, o);
    __shared__ float sh[8];
    if ((threadIdx.x & 31) == 0) sh[threadIdx.x >> 5] = s;
    __syncthreads();
    if (threadIdx.x < 8) {
        float v = sh[threadIdx.x];
        for (int o = 4; o; o >>= 1) v += __shfl_xor_sync(0xffu, v, o);
        if (threadIdx.x == 0) g_part[blockIdx.x] = v;
    }
    if (blockIdx.x == 0 && threadIdx.x < 128) {
        int t = threadIdx.x;
        float v = l1e[t] * a1e[t];
        for (int o = 16; o; o >>= 1) v += __shfl_xor_sync(0xffffffffu, v, o);
        if ((t & 31) == 0) g_coef1[t >> 5] = v;
        if (t < 32) {
            float v2 = l2e[t] * a2e[t];
            for (int o = 16; o; o >>= 1) v2 += __shfl_xor_sync(0xffffffffu, v2, o);
            if (t == 0) g_coef2 = v2;
        }
    }
}

// ---------------------------------------------------------------------------
// bucket scatter (atomicAdd = histogram), 4 edges/thread.
// Blocks touching self-loop range reduce the 512 easum partials in-block
// (deterministic tree) -> s_loopea.
__global__ void __launch_bounds__(256) k_scatter(const int* __restrict__ eidx,
                                                 const float* __restrict__ eattr) {
    __shared__ float s_loopea;
    if ((blockIdx.x + 1) * 1024 > EE) {   // this block may handle self-loops
        int t = threadIdx.x, lane = t & 31, w = t >> 5;
        float v = g_part[t] + g_part[t + 256];
        for (int o = 16; o; o >>= 1) v += __shfl_xor_sync(0xffffffffu, v, o);
        __shared__ float sh[8];
        if (lane == 0) sh[w] = v;
        __syncthreads();
        if (t < 8) {
            float u = sh[t];
            for (int o = 4; o; o >>= 1) u += __shfl_xor_sync(0xffu, u, o);
            if (t == 0) s_loopea = u * (1.0f / EE);
        }
        __syncthreads();
    }

    int i0 = (blockIdx.x * blockDim.x + threadIdx.x) * 4;
    if (i0 >= ETOT) return;
    if (i0 + 3 < EE) {
        int4 sv = *(const int4*)&eidx[i0];
        int4 dv = *(const int4*)&eidx[EE + i0];
        float4 av = *(const float4*)&eattr[i0];
        int p0 = atomicAdd(&g_cnt[dv.x], 1);
        int p1 = atomicAdd(&g_cnt[dv.y], 1);
        int p2 = atomicAdd(&g_cnt[dv.z], 1);
        int p3 = atomicAdd(&g_cnt[dv.w], 1);
        if (p0 < CAP) g_es2[dv.x * CAP + p0] = make_int2(sv.x, __float_as_int(av.x));
        if (p1 < CAP) g_es2[dv.y * CAP + p1] = make_int2(sv.y, __float_as_int(av.y));
        if (p2 < CAP) g_es2[dv.z * CAP + p2] = make_int2(sv.z, __float_as_int(av.z));
        if (p3 < CAP) g_es2[dv.w * CAP + p3] = make_int2(sv.w, __float_as_int(av.w));
    } else {
        #pragma unroll 1
        for (int q = 0; q < 4; q++) {
            int i = i0 + q;
            if (i >= ETOT) break;
            int s, d; float ea;
            if (i < EE) { s = eidx[i]; d = eidx[EE + i]; ea = eattr[i]; }
            else        { s = i - EE;  d = s;            ea = s_loopea; }
            int pos = atomicAdd(&g_cnt[d], 1);
            if (pos < CAP) g_es2[d * CAP + pos] = make_int2(s, __float_as_int(ea));
        }
    }
}

// ---------------------------------------------------------------------------
// xl1 = x @ W1 (128x128), f32x2 FMA, 32 nodes/block, fused attention dots.
__global__ void __launch_bounds__(128) k_lin1(
    const float* __restrict__ x, const float* __restrict__ w,
    const float* __restrict__ a1s, const float* __restrict__ a1d) {
    __shared__ float sxT[FIN * 36];
    int t = threadIdx.x;
    int lane = t & 31, wid = t >> 5;
    int nbase = blockIdx.x * 32;

    #pragma unroll
    for (int jj = 0; jj < 8; jj++) {
        int j = wid * 8 + jj;
        int n = nbase + j;
        const float* xr = x + (long)min(n, NN - 1) * FIN;
        #pragma unroll
        for (int c = 0; c < 4; c++) {
            int k = c * 32 + lane;
            sxT[k * 36 + j] = (n < NN) ? xr[k] : 0.f;
        }
    }
    __syncthreads();

    unsigned long long acc[16];
    #pragma unroll
    for (int p = 0; p < 16; p++) acc[p] = 0ull;
    const int col = t;
    #pragma unroll 4
    for (int k = 0; k < FIN; k++) {
        float wv = w[k * F1 + col];
        unsigned long long wv2;
        asm("mov.b64 %0, {%1, %1};" : "=l"(wv2) : "f"(wv));
        #pragma unroll
        for (int jg = 0; jg < 8; jg++) {
            ulonglong2 xv = *(const ulonglong2*)&sxT[k * 36 + jg * 4];
            FMA2(acc[jg * 2 + 0], xv.x, wv2);
            FMA2(acc[jg * 2 + 1], xv.y, wv2);
        }
    }

    float sA = a1s[col], sD = a1d[col];
    #pragma unroll
    for (int p = 0; p < 16; p++) {
        float lo, hi;
        asm("mov.b64 {%0, %1}, %2;" : "=f"(lo), "=f"(hi) : "l"(acc[p]));
        int n0 = nbase + p * 2;
        if (n0 < NN)     g_xl1h[(long)n0 * F1 + col]       = __float2half_rn(lo);
        if (n0 + 1 < NN) g_xl1h[(long)(n0 + 1) * F1 + col] = __float2half_rn(hi);
        float vs0 = lo * sA, vd0 = lo * sD, vs1 = hi * sA, vd1 = hi * sD;
        #pragma unroll
        for (int o = 16; o; o >>= 1) {
            vs0 += __shfl_xor_sync(0xffffffffu, vs0, o);
            vd0 += __shfl_xor_sync(0xffffffffu, vd0, o);
            vs1 += __shfl_xor_sync(0xffffffffu, vs1, o);
            vd1 += __shfl_xor_sync(0xffffffffu, vd1, o);
        }
        if (lane == 0 && n0 < NN) {
            g_asrc1[n0 * HEADS + wid] = vs0;
            g_adst1[n0 * HEADS + wid] = vd0;
            if (n0 + 1 < NN) {
                g_asrc1[(n0 + 1) * HEADS + wid] = vs1;
                g_adst1[(n0 + 1) * HEADS + wid] = vd1;
            }
        }
    }
}

// ---------------------------------------------------------------------------
// FUSED edge1 + lin2 (proven x2 loop, bucket indexing). 512 thr = 16 nodes.
__global__ void __launch_bounds__(512) k_edge1l2(
    const float* __restrict__ bias1, const float* __restrict__ w2,
    const float* __restrict__ a2s, const float* __restrict__ a2d) {
    __shared__ float sw2[F1 * OUTC];   // 16KB
    for (int i = threadIdx.x; i < F1 * OUTC; i += 512) sw2[i] = w2[i];
    __syncthreads();

    int d = blockIdx.x * 16 + (threadIdx.x >> 5);
    if (d >= NN) return;
    int l = threadIdx.x & 31;
    int h = l >> 3;
    int beg = d * CAP;
    int end = beg + min(g_cnt[d], CAP);
    float adst = g_adst1[d * HEADS + h];
    float cf = g_coef1[h];
    float4 acc = make_float4(0.f, 0.f, 0.f, 0.f);
    float den = 0.f;
    int j = beg;
    for (; j + 2 <= end; j += 2) {
        int2 e0 = g_es2[j], e1 = g_es2[j + 1];
        float as0 = g_asrc1[e0.x * HEADS + h];
        float as1 = g_asrc1[e1.x * HEADS + h];
        uint2 p0 = *(const uint2*)(g_xl1h + (long)e0.x * F1 + l * 4);
        uint2 p1 = *(const uint2*)(g_xl1h + (long)e1.x * F1 + l * 4);
        float al0 = as0 + adst + __int_as_float(e0.y) * cf;
        float al1 = as1 + adst + __int_as_float(e1.y) * cf;
        al0 = al0 > 0.f ? al0 : 0.2f * al0;
        al1 = al1 > 0.f ? al1 : 0.2f * al1;
        float ex0 = __expf(al0), ex1 = __expf(al1);
        den += ex0 + ex1;
        float2 a0 = __half22float2(*reinterpret_cast<__half2*>(&p0.x));
        float2 b0 = __half22float2(*reinterpret_cast<__half2*>(&p0.y));
        float2 a1 = __half22float2(*reinterpret_cast<__half2*>(&p1.x));
        float2 b1 = __half22float2(*reinterpret_cast<__half2*>(&p1.y));
        acc.x += ex0 * a0.x + ex1 * a1.x;
        acc.y += ex0 * a0.y + ex1 * a1.y;
        acc.z += ex0 * b0.x + ex1 * b1.x;
        acc.w += ex0 * b0.y + ex1 * b1.y;
    }
    if (j < end) {
        int2 e0 = g_es2[j];
        float as0 = g_asrc1[e0.x * HEADS + h];
        uint2 p0 = *(const uint2*)(g_xl1h + (long)e0.x * F1 + l * 4);
        float al0 = as0 + adst + __int_as_float(e0.y) * cf;
        al0 = al0 > 0.f ? al0 : 0.2f * al0;
        float ex0 = __expf(al0);
        den += ex0;
        float2 a0 = __half22float2(*reinterpret_cast<__half2*>(&p0.x));
        float2 b0 = __half22float2(*reinterpret_cast<__half2*>(&p0.y));
        acc.x += ex0 * a0.x; acc.y += ex0 * a0.y;
        acc.z += ex0 * b0.x; acc.w += ex0 * b0.y;
    }
    float inv = 1.f / den;
    float4 b = *(const float4*)&bias1[l * 4];
    float4 v;
    v.x = acc.x * inv + b.x; v.y = acc.y * inv + b.y;
    v.z = acc.z * inv + b.z; v.w = acc.w * inv + b.w;
    v.x = v.x > 0.f ? v.x : expm1f(v.x);
    v.y = v.y > 0.f ? v.y : expm1f(v.y);
    v.z = v.z > 0.f ? v.z : expm1f(v.z);
    v.w = v.w > 0.f ? v.w : expm1f(v.w);

    // h @ W2: lane sl holds h[4sl..4sl+3]; output col = l
    float o2 = 0.f;
    #pragma unroll
    for (int sl = 0; sl < 32; sl++) {
        float h0 = __shfl_sync(0xffffffffu, v.x, sl);
        float h1 = __shfl_sync(0xffffffffu, v.y, sl);
        float h2 = __shfl_sync(0xffffffffu, v.z, sl);
        float h3 = __shfl_sync(0xffffffffu, v.w, sl);
        o2 += h0 * sw2[(sl * 4 + 0) * OUTC + l];
        o2 += h1 * sw2[(sl * 4 + 1) * OUTC + l];
        o2 += h2 * sw2[(sl * 4 + 2) * OUTC + l];
        o2 += h3 * sw2[(sl * 4 + 3) * OUTC + l];
    }
    g_xl2[d * OUTC + l] = o2;
    float vs = o2 * a2s[l], vd = o2 * a2d[l];
    #pragma unroll
    for (int o = 16; o; o >>= 1) {
        vs += __shfl_xor_sync(0xffffffffu, vs, o);
        vd += __shfl_xor_sync(0xffffffffu, vd, o);
    }
    if (l == 0) { g_asrc2[d] = vs; g_adst2[d] = vd; }
}

// ---------------------------------------------------------------------------
// Gather edge pass layer2 (proven x2 loop, bucket indexing). 512 threads.
__global__ void __launch_bounds__(512) k_edge2g(float* __restrict__ out,
                                                const float* __restrict__ bias2) {
    int d = blockIdx.x * 16 + (threadIdx.x >> 5);
    if (d >= NN) return;
    int l = threadIdx.x & 31;
    int beg = d * CAP;
    int end = beg + min(g_cnt[d], CAP);
    float adst = g_adst2[d];
    float cf = g_coef2;
    float acc = 0.f, den = 0.f;
    int j = beg;
    for (; j + 2 <= end; j += 2) {
        int2 e0 = g_es2[j], e1 = g_es2[j + 1];
        float as0 = g_asrc2[e0.x];
        float as1 = g_asrc2[e1.x];
        float v0 = g_xl2[e0.x * OUTC + l];
        float v1 = g_xl2[e1.x * OUTC + l];
        float al0 = as0 + adst + __int_as_float(e0.y) * cf;
        float al1 = as1 + adst + __int_as_float(e1.y) * cf;
        al0 = al0 > 0.f ? al0 : 0.2f * al0;
        al1 = al1 > 0.f ? al1 : 0.2f * al1;
        float ex0 = __expf(al0), ex1 = __expf(al1);
        den += ex0 + ex1;
        acc += ex0 * v0 + ex1 * v1;
    }
    if (j < end) {
        int2 e0 = g_es2[j];
        float al0 = g_asrc2[e0.x] + adst + __int_as_float(e0.y) * cf;
        al0 = al0 > 0.f ? al0 : 0.2f * al0;
        float ex0 = __expf(al0);
        den += ex0;
        acc += ex0 * g_xl2[e0.x * OUTC + l];
    }
    out[(long)d * OUTC + l] = acc / den + bias2[l];
}

// ---------------------------------------------------------------------------
extern "C" void kernel_launch(void* const* d_in, const int* in_sizes, int n_in,
                              void* d_out, int out_size) {
    const float* x        = (const float*)d_in[0];
    const int*   eidx     = (const int*)  d_in[1];
    const float* eattr    = (const float*)d_in[2];
    const float* lin1_w   = (const float*)d_in[3];
    const float* att1_src = (const float*)d_in[4];
    const float* att1_dst = (const float*)d_in[5];
    const float* lin1_ew  = (const float*)d_in[6];
    const float* att1_e   = (const float*)d_in[7];
    const float* bias1    = (const float*)d_in[8];
    const float* lin2_w   = (const float*)d_in[9];
    const float* att2_src = (const float*)d_in[10];
    const float* att2_dst = (const float*)d_in[11];
    const float* lin2_ew  = (const float*)d_in[12];
    const float* att2_e   = (const float*)d_in[13];
    const float* bias2    = (const float*)d_in[14];
    float* out = (float*)d_out;

    static cudaStream_t sB = nullptr;
    static cudaEvent_t evFork = nullptr, evB = nullptr;
    static bool streamsOk = false;
    if (sB == nullptr && !streamsOk) {
        bool ok = (cudaStreamCreateWithFlags(&sB, cudaStreamNonBlocking) == cudaSuccess)
               && (cudaEventCreateWithFlags(&evFork, cudaEventDisableTiming) == cudaSuccess)
               && (cudaEventCreateWithFlags(&evB, cudaEventDisableTiming) == cudaSuccess);
        streamsOk = ok;
        if (!ok) sB = nullptr;
    }

    if (streamsOk) {
        // launch idx0: lin1 on side stream (independent of edge bucketing)
        cudaEventRecord(evFork, 0);
        cudaStreamWaitEvent(sB, evFork, 0);
        k_lin1<<<(NN + 31) / 32, 128, 0, sB>>>(x, lin1_w, att1_src, att1_dst);
        cudaEventRecord(evB, sB);

        // idx1: prep (zero counts + easum partials + coefs), idx2: scatter
        k_prep<<<512, 256>>>(eattr, lin1_ew, att1_e, lin2_ew, att2_e);
        k_scatter<<<(ETOT / 4 + 255) / 256, 256>>>(eidx, eattr);

        // idx3: edge1l2 (ncu -s5 profiles this one), idx4: edge2g
        cudaStreamWaitEvent(0, evB, 0);
        k_edge1l2<<<(NN + 15) / 16, 512>>>(bias1, lin2_w, att2_src, att2_dst);
        k_edge2g<<<(NN + 15) / 16, 512>>>(out, bias2);
    } else {
        // serial fallback (same kernels, one stream)
        k_lin1<<<(NN + 31) / 32, 128>>>(x, lin1_w, att1_src, att1_dst);
        k_prep<<<512, 256>>>(eattr, lin1_ew, att1_e, lin2_ew, att2_e);
        k_scatter<<<(ETOT / 4 + 255) / 256, 256>>>(eidx, eattr);
        k_edge1l2<<<(NN + 15) / 16, 512>>>(bias1, lin2_w, att2_src, att2_dst);
        k_edge2g<<<(NN + 15) / 16, 512>>>(out, bias2);
    }
}

// round 13
// speedup vs baseline: 1.0363x; 1.0363x over previous
#include <cuda_runtime.h>
#include <cuda_fp16.h>

#define NN 50000
#define EE 800000
#define ETOT (EE + NN)          // 850000
#define FIN 128
#define HID 32
#define HEADS 4
#define F1 128                  // HEADS*HID
#define OUTC 32
#define CAP 64                  // bucket capacity per node (max degree ~36)

// ---- scratch (no allocs allowed) ----
__device__ __half g_xl1h[NN * F1];      // layer1 transformed features (fp16)
__device__ __half g_h1h[NN * F1];       // elu(normalized out1 + bias1) (fp16)
__device__ __align__(16) float g_asrc1[NN * HEADS];
__device__ __align__(16) float g_adst1[NN * HEADS];
__device__ float g_xl2[NN * OUTC];
__device__ float g_asrc2[NN];
__device__ float g_adst2[NN];
__device__ float g_part[512];
__device__ __align__(16) float g_coef1[4];
__device__ float g_coef2;
// bucketed edge store: node d owns slots [d*CAP, d*CAP+cnt[d])
__device__ int  g_cnt[NN];
__device__ __align__(16) int2 g_es2[NN * CAP];   // (src, ea_bits)

#define FMA2(d, a, b) asm("fma.rn.f32x2 %0, %1, %2, %0;" : "+l"(d) : "l"(a), "l"(b))

// ---------------------------------------------------------------------------
// prep: zero g_cnt + easum block partials + coef dots (one kernel)
__global__ void __launch_bounds__(256) k_prep(
    const float* __restrict__ ea,
    const float* __restrict__ l1e, const float* __restrict__ a1e,
    const float* __restrict__ l2e, const float* __restrict__ a2e) {
    int t0 = blockIdx.x * blockDim.x + threadIdx.x;
    int stride = gridDim.x * blockDim.x;   // 512*256 = 131072
    for (int i = t0; i < NN; i += stride) g_cnt[i] = 0;

    float s = 0.f;
    for (int i = t0; i < EE; i += stride) s += ea[i];
    for (int o = 16; o; o >>= 1) s += __shfl_xor_sync(0xffffffffu, s, o);
    __shared__ float sh[8];
    if ((threadIdx.x & 31) == 0) sh[threadIdx.x >> 5] = s;
    __syncthreads();
    if (threadIdx.x < 8) {
        float v = sh[threadIdx.x];
        for (int o = 4; o; o >>= 1) v += __shfl_xor_sync(0xffu, v, o);
        if (threadIdx.x == 0) g_part[blockIdx.x] = v;
    }
    if (blockIdx.x == 0 && threadIdx.x < 128) {
        int t = threadIdx.x;
        float v = l1e[t] * a1e[t];
        for (int o = 16; o; o >>= 1) v += __shfl_xor_sync(0xffffffffu, v, o);
        if ((t & 31) == 0) g_coef1[t >> 5] = v;
        if (t < 32) {
            float v2 = l2e[t] * a2e[t];
            for (int o = 16; o; o >>= 1) v2 += __shfl_xor_sync(0xffffffffu, v2, o);
            if (t == 0) g_coef2 = v2;
        }
    }
}

// ---------------------------------------------------------------------------
// bucket scatter (atomicAdd = histogram), 4 edges/thread; late blocks also
// reduce easum partials for the self-loop fill value.
__global__ void __launch_bounds__(256) k_scatter(const int* __restrict__ eidx,
                                                 const float* __restrict__ eattr) {
    __shared__ float s_loopea;
    if ((blockIdx.x + 1) * 1024 > EE) {
        int t = threadIdx.x, lane = t & 31, w = t >> 5;
        float v = g_part[t] + g_part[t + 256];
        for (int o = 16; o; o >>= 1) v += __shfl_xor_sync(0xffffffffu, v, o);
        __shared__ float sh[8];
        if (lane == 0) sh[w] = v;
        __syncthreads();
        if (t < 8) {
            float u = sh[t];
            for (int o = 4; o; o >>= 1) u += __shfl_xor_sync(0xffu, u, o);
            if (t == 0) s_loopea = u * (1.0f / EE);
        }
        __syncthreads();
    }

    int i0 = (blockIdx.x * blockDim.x + threadIdx.x) * 4;
    if (i0 >= ETOT) return;
    if (i0 + 3 < EE) {
        int4 sv = *(const int4*)&eidx[i0];
        int4 dv = *(const int4*)&eidx[EE + i0];
        float4 av = *(const float4*)&eattr[i0];
        int p0 = atomicAdd(&g_cnt[dv.x], 1);
        int p1 = atomicAdd(&g_cnt[dv.y], 1);
        int p2 = atomicAdd(&g_cnt[dv.z], 1);
        int p3 = atomicAdd(&g_cnt[dv.w], 1);
        if (p0 < CAP) g_es2[dv.x * CAP + p0] = make_int2(sv.x, __float_as_int(av.x));
        if (p1 < CAP) g_es2[dv.y * CAP + p1] = make_int2(sv.y, __float_as_int(av.y));
        if (p2 < CAP) g_es2[dv.z * CAP + p2] = make_int2(sv.z, __float_as_int(av.z));
        if (p3 < CAP) g_es2[dv.w * CAP + p3] = make_int2(sv.w, __float_as_int(av.w));
    } else {
        #pragma unroll 1
        for (int q = 0; q < 4; q++) {
            int i = i0 + q;
            if (i >= ETOT) break;
            int s, d; float ea;
            if (i < EE) { s = eidx[i]; d = eidx[EE + i]; ea = eattr[i]; }
            else        { s = i - EE;  d = s;            ea = s_loopea; }
            int pos = atomicAdd(&g_cnt[d], 1);
            if (pos < CAP) g_es2[d * CAP + pos] = make_int2(s, __float_as_int(ea));
        }
    }
}

// ---------------------------------------------------------------------------
// xl1 = x @ W1 (128x128), f32x2 FMA, 32 nodes/block, fused attention dots.
__global__ void __launch_bounds__(128) k_lin1(
    const float* __restrict__ x, const float* __restrict__ w,
    const float* __restrict__ a1s, const float* __restrict__ a1d) {
    __shared__ float sxT[FIN * 36];
    int t = threadIdx.x;
    int lane = t & 31, wid = t >> 5;
    int nbase = blockIdx.x * 32;

    #pragma unroll
    for (int jj = 0; jj < 8; jj++) {
        int j = wid * 8 + jj;
        int n = nbase + j;
        const float* xr = x + (long)min(n, NN - 1) * FIN;
        #pragma unroll
        for (int c = 0; c < 4; c++) {
            int k = c * 32 + lane;
            sxT[k * 36 + j] = (n < NN) ? xr[k] : 0.f;
        }
    }
    __syncthreads();

    unsigned long long acc[16];
    #pragma unroll
    for (int p = 0; p < 16; p++) acc[p] = 0ull;
    const int col = t;
    #pragma unroll 4
    for (int k = 0; k < FIN; k++) {
        float wv = w[k * F1 + col];
        unsigned long long wv2;
        asm("mov.b64 %0, {%1, %1};" : "=l"(wv2) : "f"(wv));
        #pragma unroll
        for (int jg = 0; jg < 8; jg++) {
            ulonglong2 xv = *(const ulonglong2*)&sxT[k * 36 + jg * 4];
            FMA2(acc[jg * 2 + 0], xv.x, wv2);
            FMA2(acc[jg * 2 + 1], xv.y, wv2);
        }
    }

    float sA = a1s[col], sD = a1d[col];
    #pragma unroll
    for (int p = 0; p < 16; p++) {
        float lo, hi;
        asm("mov.b64 {%0, %1}, %2;" : "=f"(lo), "=f"(hi) : "l"(acc[p]));
        int n0 = nbase + p * 2;
        if (n0 < NN)     g_xl1h[(long)n0 * F1 + col]       = __float2half_rn(lo);
        if (n0 + 1 < NN) g_xl1h[(long)(n0 + 1) * F1 + col] = __float2half_rn(hi);
        float vs0 = lo * sA, vd0 = lo * sD, vs1 = hi * sA, vd1 = hi * sD;
        #pragma unroll
        for (int o = 16; o; o >>= 1) {
            vs0 += __shfl_xor_sync(0xffffffffu, vs0, o);
            vd0 += __shfl_xor_sync(0xffffffffu, vd0, o);
            vs1 += __shfl_xor_sync(0xffffffffu, vs1, o);
            vd1 += __shfl_xor_sync(0xffffffffu, vd1, o);
        }
        if (lane == 0 && n0 < NN) {
            g_asrc1[n0 * HEADS + wid] = vs0;
            g_adst1[n0 * HEADS + wid] = vd0;
            if (n0 + 1 < NN) {
                g_asrc1[(n0 + 1) * HEADS + wid] = vs1;
                g_adst1[(n0 + 1) * HEADS + wid] = vd1;
            }
        }
    }
}

// ---------------------------------------------------------------------------
// Gather edge pass layer1 (proven x2 loop). Epilogue: normalize+bias+ELU ->
// fp16 h store only (lin2 split out). 512 thr = 16 nodes/block.
__global__ void __launch_bounds__(512) k_edge1(const float* __restrict__ bias1) {
    int d = blockIdx.x * 16 + (threadIdx.x >> 5);
    if (d >= NN) return;
    int l = threadIdx.x & 31;
    int h = l >> 3;
    int beg = d * CAP;
    int end = beg + min(g_cnt[d], CAP);
    float adst = g_adst1[d * HEADS + h];
    float cf = g_coef1[h];
    float4 acc = make_float4(0.f, 0.f, 0.f, 0.f);
    float den = 0.f;
    int j = beg;
    for (; j + 2 <= end; j += 2) {
        int2 e0 = g_es2[j], e1 = g_es2[j + 1];
        float as0 = g_asrc1[e0.x * HEADS + h];
        float as1 = g_asrc1[e1.x * HEADS + h];
        uint2 p0 = *(const uint2*)(g_xl1h + (long)e0.x * F1 + l * 4);
        uint2 p1 = *(const uint2*)(g_xl1h + (long)e1.x * F1 + l * 4);
        float al0 = as0 + adst + __int_as_float(e0.y) * cf;
        float al1 = as1 + adst + __int_as_float(e1.y) * cf;
        al0 = al0 > 0.f ? al0 : 0.2f * al0;
        al1 = al1 > 0.f ? al1 : 0.2f * al1;
        float ex0 = __expf(al0), ex1 = __expf(al1);
        den += ex0 + ex1;
        float2 a0 = __half22float2(*reinterpret_cast<__half2*>(&p0.x));
        float2 b0 = __half22float2(*reinterpret_cast<__half2*>(&p0.y));
        float2 a1 = __half22float2(*reinterpret_cast<__half2*>(&p1.x));
        float2 b1 = __half22float2(*reinterpret_cast<__half2*>(&p1.y));
        acc.x += ex0 * a0.x + ex1 * a1.x;
        acc.y += ex0 * a0.y + ex1 * a1.y;
        acc.z += ex0 * b0.x + ex1 * b1.x;
        acc.w += ex0 * b0.y + ex1 * b1.y;
    }
    if (j < end) {
        int2 e0 = g_es2[j];
        float as0 = g_asrc1[e0.x * HEADS + h];
        uint2 p0 = *(const uint2*)(g_xl1h + (long)e0.x * F1 + l * 4);
        float al0 = as0 + adst + __int_as_float(e0.y) * cf;
        al0 = al0 > 0.f ? al0 : 0.2f * al0;
        float ex0 = __expf(al0);
        den += ex0;
        float2 a0 = __half22float2(*reinterpret_cast<__half2*>(&p0.x));
        float2 b0 = __half22float2(*reinterpret_cast<__half2*>(&p0.y));
        acc.x += ex0 * a0.x; acc.y += ex0 * a0.y;
        acc.z += ex0 * b0.x; acc.w += ex0 * b0.y;
    }
    float inv = 1.f / den;
    float4 b = *(const float4*)&bias1[l * 4];
    float4 v;
    v.x = acc.x * inv + b.x; v.y = acc.y * inv + b.y;
    v.z = acc.z * inv + b.z; v.w = acc.w * inv + b.w;
    v.x = v.x > 0.f ? v.x : expm1f(v.x);
    v.y = v.y > 0.f ? v.y : expm1f(v.y);
    v.z = v.z > 0.f ? v.z : expm1f(v.z);
    v.w = v.w > 0.f ? v.w : expm1f(v.w);

    __half2 h01 = __floats2half2_rn(v.x, v.y);
    __half2 h23 = __floats2half2_rn(v.z, v.w);
    uint2 st;
    st.x = *reinterpret_cast<unsigned*>(&h01);
    st.y = *reinterpret_cast<unsigned*>(&h23);
    *(uint2*)(g_h1h + (long)d * F1 + l * 4) = st;
}

// ---------------------------------------------------------------------------
// xl2 = h @ W2 (128x32): register-tiled GEMM, 32 nodes/block, 128 threads.
// Thread t: col = t&31, node-group jg = t>>5 (8 nodes). Fused att2 dots.
__global__ void __launch_bounds__(128) k_lin2(
    const float* __restrict__ w2, const float* __restrict__ a2s,
    const float* __restrict__ a2d) {
    __shared__ float sxT[FIN * 36];   // [k][node(+pad)] of h
    int t = threadIdx.x;
    int lane = t & 31, wid = t >> 5;
    int nbase = blockIdx.x * 32;

    // stage h^T: warp handles 8 nodes; lane loads halves [4l..4l+3] of node j
    #pragma unroll
    for (int jj = 0; jj < 8; jj++) {
        int j = wid * 8 + jj;
        int n = nbase + j;
        uint2 pv = (n < NN) ? *(const uint2*)(g_h1h + (long)n * F1 + lane * 4)
                            : make_uint2(0u, 0u);
        float2 f0 = __half22float2(*reinterpret_cast<__half2*>(&pv.x));
        float2 f1 = __half22float2(*reinterpret_cast<__half2*>(&pv.y));
        sxT[(lane * 4 + 0) * 36 + j] = f0.x;
        sxT[(lane * 4 + 1) * 36 + j] = f0.y;
        sxT[(lane * 4 + 2) * 36 + j] = f1.x;
        sxT[(lane * 4 + 3) * 36 + j] = f1.y;
    }
    __syncthreads();

    const int col = lane;
    const int jg = wid;           // node group: nodes jg*8..jg*8+7
    unsigned long long acc2[4];
    #pragma unroll
    for (int p = 0; p < 4; p++) acc2[p] = 0ull;
    #pragma unroll 4
    for (int k = 0; k < FIN; k++) {
        float wv = w2[k * OUTC + col];
        unsigned long long wv2;
        asm("mov.b64 %0, {%1, %1};" : "=l"(wv2) : "f"(wv));
        ulonglong2 xv0 = *(const ulonglong2*)&sxT[k * 36 + jg * 8];
        ulonglong2 xv1 = *(const ulonglong2*)&sxT[k * 36 + jg * 8 + 4];
        FMA2(acc2[0], xv0.x, wv2);
        FMA2(acc2[1], xv0.y, wv2);
        FMA2(acc2[2], xv1.x, wv2);
        FMA2(acc2[3], xv1.y, wv2);
    }

    float sA = a2s[col], sD = a2d[col];
    #pragma unroll
    for (int p = 0; p < 4; p++) {
        float lo, hi;
        asm("mov.b64 {%0, %1}, %2;" : "=f"(lo), "=f"(hi) : "l"(acc2[p]));
        int n0 = nbase + jg * 8 + p * 2;
        if (n0 < NN)     g_xl2[n0 * OUTC + col]       = lo;
        if (n0 + 1 < NN) g_xl2[(n0 + 1) * OUTC + col] = hi;
        float vs0 = lo * sA, vd0 = lo * sD, vs1 = hi * sA, vd1 = hi * sD;
        #pragma unroll
        for (int o = 16; o; o >>= 1) {
            vs0 += __shfl_xor_sync(0xffffffffu, vs0, o);
            vd0 += __shfl_xor_sync(0xffffffffu, vd0, o);
            vs1 += __shfl_xor_sync(0xffffffffu, vs1, o);
            vd1 += __shfl_xor_sync(0xffffffffu, vd1, o);
        }
        if (lane == 0 && n0 < NN) {
            g_asrc2[n0] = vs0;
            g_adst2[n0] = vd0;
            if (n0 + 1 < NN) { g_asrc2[n0 + 1] = vs1; g_adst2[n0 + 1] = vd1; }
        }
    }
}

// ---------------------------------------------------------------------------
// Gather edge pass layer2 (proven x2 loop, bucket indexing). 512 threads.
__global__ void __launch_bounds__(512) k_edge2g(float* __restrict__ out,
                                                const float* __restrict__ bias2) {
    int d = blockIdx.x * 16 + (threadIdx.x >> 5);
    if (d >= NN) return;
    int l = threadIdx.x & 31;
    int beg = d * CAP;
    int end = beg + min(g_cnt[d], CAP);
    float adst = g_adst2[d];
    float cf = g_coef2;
    float acc = 0.f, den = 0.f;
    int j = beg;
    for (; j + 2 <= end; j += 2) {
        int2 e0 = g_es2[j], e1 = g_es2[j + 1];
        float as0 = g_asrc2[e0.x];
        float as1 = g_asrc2[e1.x];
        float v0 = g_xl2[e0.x * OUTC + l];
        float v1 = g_xl2[e1.x * OUTC + l];
        float al0 = as0 + adst + __int_as_float(e0.y) * cf;
        float al1 = as1 + adst + __int_as_float(e1.y) * cf;
        al0 = al0 > 0.f ? al0 : 0.2f * al0;
        al1 = al1 > 0.f ? al1 : 0.2f * al1;
        float ex0 = __expf(al0), ex1 = __expf(al1);
        den += ex0 + ex1;
        acc += ex0 * v0 + ex1 * v1;
    }
    if (j < end) {
        int2 e0 = g_es2[j];
        float al0 = g_asrc2[e0.x] + adst + __int_as_float(e0.y) * cf;
        al0 = al0 > 0.f ? al0 : 0.2f * al0;
        float ex0 = __expf(al0);
        den += ex0;
        acc += ex0 * g_xl2[e0.x * OUTC + l];
    }
    out[(long)d * OUTC + l] = acc / den + bias2[l];
}

// ---------------------------------------------------------------------------
extern "C" void kernel_launch(void* const* d_in, const int* in_sizes, int n_in,
                              void* d_out, int out_size) {
    const float* x        = (const float*)d_in[0];
    const int*   eidx     = (const int*)  d_in[1];
    const float* eattr    = (const float*)d_in[2];
    const float* lin1_w   = (const float*)d_in[3];
    const float* att1_src = (const float*)d_in[4];
    const float* att1_dst = (const float*)d_in[5];
    const float* lin1_ew  = (const float*)d_in[6];
    const float* att1_e   = (const float*)d_in[7];
    const float* bias1    = (const float*)d_in[8];
    const float* lin2_w   = (const float*)d_in[9];
    const float* att2_src = (const float*)d_in[10];
    const float* att2_dst = (const float*)d_in[11];
    const float* lin2_ew  = (const float*)d_in[12];
    const float* att2_e   = (const float*)d_in[13];
    const float* bias2    = (const float*)d_in[14];
    float* out = (float*)d_out;

    static cudaStream_t sB = nullptr;
    static cudaEvent_t evFork = nullptr, evB = nullptr;
    static bool streamsOk = false;
    if (sB == nullptr && !streamsOk) {
        bool ok = (cudaStreamCreateWithFlags(&sB, cudaStreamNonBlocking) == cudaSuccess)
               && (cudaEventCreateWithFlags(&evFork, cudaEventDisableTiming) == cudaSuccess)
               && (cudaEventCreateWithFlags(&evB, cudaEventDisableTiming) == cudaSuccess);
        streamsOk = ok;
        if (!ok) sB = nullptr;
    }

    if (streamsOk) {
        // idx0: lin1 on side stream (independent of edge bucketing)
        cudaEventRecord(evFork, 0);
        cudaStreamWaitEvent(sB, evFork, 0);
        k_lin1<<<(NN + 31) / 32, 128, 0, sB>>>(x, lin1_w, att1_src, att1_dst);
        cudaEventRecord(evB, sB);

        // idx1: prep, idx2: scatter
        k_prep<<<512, 256>>>(eattr, lin1_ew, att1_e, lin2_ew, att2_e);
        k_scatter<<<(ETOT / 4 + 255) / 256, 256>>>(eidx, eattr);

        // idx3: edge1 (ncu -s5 profiles this), idx4: lin2, idx5: edge2g
        cudaStreamWaitEvent(0, evB, 0);
        k_edge1<<<(NN + 15) / 16, 512>>>(bias1);
        k_lin2<<<(NN + 31) / 32, 128>>>(lin2_w, att2_src, att2_dst);
        k_edge2g<<<(NN + 15) / 16, 512>>>(out, bias2);
    } else {
        // serial fallback
        k_lin1<<<(NN + 31) / 32, 128>>>(x, lin1_w, att1_src, att1_dst);
        k_prep<<<512, 256>>>(eattr, lin1_ew, att1_e, lin2_ew, att2_e);
        k_scatter<<<(ETOT / 4 + 255) / 256, 256>>>(eidx, eattr);
        k_edge1<<<(NN + 15) / 16, 512>>>(bias1);
        k_lin2<<<(NN + 31) / 32, 128>>>(lin2_w, att2_src, att2_dst);
        k_edge2g<<<(NN + 15) / 16, 512>>>(out, bias2);
    }
}

// round 14
// speedup vs baseline: 1.0945x; 1.0561x over previous
#include <cuda_runtime.h>
#include <cuda_fp16.h>

#define NN 50000
#define EE 800000
#define ETOT (EE + NN)          // 850000
#define FIN 128
#define HID 32
#define HEADS 4
#define F1 128                  // HEADS*HID
#define OUTC 32
#define CAP 64                  // bucket capacity per node (max degree ~36)
#define LOG2E 1.4426950408889634f

// ---- scratch (no allocs allowed) ----
__device__ __align__(16) __half g_xl1h[NN * F1];  // layer1 features (fp16)
__device__ __align__(16) __half g_h1h[NN * F1];   // elu(h1) (fp16)
__device__ __align__(16) float g_asrc1[NN * HEADS];  // pre-scaled by log2e
__device__ __align__(16) float g_adst1[NN * HEADS];
__device__ float g_xl2[NN * OUTC];
__device__ float g_asrc2[NN];                     // pre-scaled by log2e
__device__ float g_adst2[NN];
__device__ float g_part[512];
__device__ __align__(16) float g_coef1[4];        // pre-scaled by log2e
__device__ float g_coef2;
// bucketed edge store: node d owns slots [d*CAP, d*CAP+cnt[d])
__device__ int  g_cnt[NN];
__device__ __align__(16) int2 g_es2[NN * CAP];    // (src, ea_bits)

#define FMA2(d, a, b) asm("fma.rn.f32x2 %0, %1, %2, %0;" : "+l"(d) : "l"(a), "l"(b))
#define EX2(r, x) asm("ex2.approx.f32 %0, %1;" : "=f"(r) : "f"(x))

// ---------------------------------------------------------------------------
// prep: zero g_cnt + easum block partials + coef dots (coefs pre-scaled)
__global__ void __launch_bounds__(256) k_prep(
    const float* __restrict__ ea,
    const float* __restrict__ l1e, const float* __restrict__ a1e,
    const float* __restrict__ l2e, const float* __restrict__ a2e) {
    int t0 = blockIdx.x * blockDim.x + threadIdx.x;
    int stride = gridDim.x * blockDim.x;   // 512*256 = 131072
    for (int i = t0; i < NN; i += stride) g_cnt[i] = 0;

    float s = 0.f;
    for (int i = t0; i < EE; i += stride) s += ea[i];
    for (int o = 16; o; o >>= 1) s += __shfl_xor_sync(0xffffffffu, s, o);
    __shared__ float sh[8];
    if ((threadIdx.x & 31) == 0) sh[threadIdx.x >> 5] = s;
    __syncthreads();
    if (threadIdx.x < 8) {
        float v = sh[threadIdx.x];
        for (int o = 4; o; o >>= 1) v += __shfl_xor_sync(0xffu, v, o);
        if (threadIdx.x == 0) g_part[blockIdx.x] = v;
    }
    if (blockIdx.x == 0 && threadIdx.x < 128) {
        int t = threadIdx.x;
        float v = l1e[t] * a1e[t];
        for (int o = 16; o; o >>= 1) v += __shfl_xor_sync(0xffffffffu, v, o);
        if ((t & 31) == 0) g_coef1[t >> 5] = v * LOG2E;
        if (t < 32) {
            float v2 = l2e[t] * a2e[t];
            for (int o = 16; o; o >>= 1) v2 += __shfl_xor_sync(0xffffffffu, v2, o);
            if (t == 0) g_coef2 = v2 * LOG2E;
        }
    }
}

// ---------------------------------------------------------------------------
// bucket scatter (atomicAdd = histogram), 4 edges/thread; late blocks also
// reduce easum partials for the self-loop fill value.
__global__ void __launch_bounds__(256) k_scatter(const int* __restrict__ eidx,
                                                 const float* __restrict__ eattr) {
    __shared__ float s_loopea;
    if ((blockIdx.x + 1) * 1024 > EE) {
        int t = threadIdx.x, lane = t & 31, w = t >> 5;
        float v = g_part[t] + g_part[t + 256];
        for (int o = 16; o; o >>= 1) v += __shfl_xor_sync(0xffffffffu, v, o);
        __shared__ float sh[8];
        if (lane == 0) sh[w] = v;
        __syncthreads();
        if (t < 8) {
            float u = sh[t];
            for (int o = 4; o; o >>= 1) u += __shfl_xor_sync(0xffu, u, o);
            if (t == 0) s_loopea = u * (1.0f / EE);
        }
        __syncthreads();
    }

    int i0 = (blockIdx.x * blockDim.x + threadIdx.x) * 4;
    if (i0 >= ETOT) return;
    if (i0 + 3 < EE) {
        int4 sv = *(const int4*)&eidx[i0];
        int4 dv = *(const int4*)&eidx[EE + i0];
        float4 av = *(const float4*)&eattr[i0];
        int p0 = atomicAdd(&g_cnt[dv.x], 1);
        int p1 = atomicAdd(&g_cnt[dv.y], 1);
        int p2 = atomicAdd(&g_cnt[dv.z], 1);
        int p3 = atomicAdd(&g_cnt[dv.w], 1);
        if (p0 < CAP) g_es2[dv.x * CAP + p0] = make_int2(sv.x, __float_as_int(av.x));
        if (p1 < CAP) g_es2[dv.y * CAP + p1] = make_int2(sv.y, __float_as_int(av.y));
        if (p2 < CAP) g_es2[dv.z * CAP + p2] = make_int2(sv.z, __float_as_int(av.z));
        if (p3 < CAP) g_es2[dv.w * CAP + p3] = make_int2(sv.w, __float_as_int(av.w));
    } else {
        #pragma unroll 1
        for (int q = 0; q < 4; q++) {
            int i = i0 + q;
            if (i >= ETOT) break;
            int s, d; float ea;
            if (i < EE) { s = eidx[i]; d = eidx[EE + i]; ea = eattr[i]; }
            else        { s = i - EE;  d = s;            ea = s_loopea; }
            int pos = atomicAdd(&g_cnt[d], 1);
            if (pos < CAP) g_es2[d * CAP + pos] = make_int2(s, __float_as_int(ea));
        }
    }
}

// ---------------------------------------------------------------------------
// xl1 = x @ W1 (128x128), f32x2 FMA, 32 nodes/block, fused attention dots
// (dots pre-scaled by log2e for exp2 in the gather).
__global__ void __launch_bounds__(128) k_lin1(
    const float* __restrict__ x, const float* __restrict__ w,
    const float* __restrict__ a1s, const float* __restrict__ a1d) {
    __shared__ float sxT[FIN * 36];
    int t = threadIdx.x;
    int lane = t & 31, wid = t >> 5;
    int nbase = blockIdx.x * 32;

    #pragma unroll
    for (int jj = 0; jj < 8; jj++) {
        int j = wid * 8 + jj;
        int n = nbase + j;
        const float* xr = x + (long)min(n, NN - 1) * FIN;
        #pragma unroll
        for (int c = 0; c < 4; c++) {
            int k = c * 32 + lane;
            sxT[k * 36 + j] = (n < NN) ? xr[k] : 0.f;
        }
    }
    __syncthreads();

    unsigned long long acc[16];
    #pragma unroll
    for (int p = 0; p < 16; p++) acc[p] = 0ull;
    const int col = t;
    #pragma unroll 4
    for (int k = 0; k < FIN; k++) {
        float wv = w[k * F1 + col];
        unsigned long long wv2;
        asm("mov.b64 %0, {%1, %1};" : "=l"(wv2) : "f"(wv));
        #pragma unroll
        for (int jg = 0; jg < 8; jg++) {
            ulonglong2 xv = *(const ulonglong2*)&sxT[k * 36 + jg * 4];
            FMA2(acc[jg * 2 + 0], xv.x, wv2);
            FMA2(acc[jg * 2 + 1], xv.y, wv2);
        }
    }

    float sA = a1s[col] * LOG2E, sD = a1d[col] * LOG2E;
    #pragma unroll
    for (int p = 0; p < 16; p++) {
        float lo, hi;
        asm("mov.b64 {%0, %1}, %2;" : "=f"(lo), "=f"(hi) : "l"(acc[p]));
        int n0 = nbase + p * 2;
        if (n0 < NN)     g_xl1h[(long)n0 * F1 + col]       = __float2half_rn(lo);
        if (n0 + 1 < NN) g_xl1h[(long)(n0 + 1) * F1 + col] = __float2half_rn(hi);
        float vs0 = lo * sA, vd0 = lo * sD, vs1 = hi * sA, vd1 = hi * sD;
        #pragma unroll
        for (int o = 16; o; o >>= 1) {
            vs0 += __shfl_xor_sync(0xffffffffu, vs0, o);
            vd0 += __shfl_xor_sync(0xffffffffu, vd0, o);
            vs1 += __shfl_xor_sync(0xffffffffu, vs1, o);
            vd1 += __shfl_xor_sync(0xffffffffu, vd1, o);
        }
        if (lane == 0 && n0 < NN) {
            g_asrc1[n0 * HEADS + wid] = vs0;
            g_adst1[n0 * HEADS + wid] = vd0;
            if (n0 + 1 < NN) {
                g_asrc1[(n0 + 1) * HEADS + wid] = vs1;
                g_adst1[(n0 + 1) * HEADS + wid] = vd1;
            }
        }
    }
}

// ---------------------------------------------------------------------------
// Gather edge pass layer1 (proven x2 loop, exp2). Epilogue: normalize+bias+
// ELU -> fp16 h store. 512 thr = 16 nodes/block.
__global__ void __launch_bounds__(512) k_edge1(const float* __restrict__ bias1) {
    int d = blockIdx.x * 16 + (threadIdx.x >> 5);
    if (d >= NN) return;
    int l = threadIdx.x & 31;
    int h = l >> 3;
    int beg = d * CAP;
    int end = beg + min(g_cnt[d], CAP);
    float adst = g_adst1[d * HEADS + h];
    float cf = g_coef1[h];
    float4 acc = make_float4(0.f, 0.f, 0.f, 0.f);
    float den = 0.f;
    int j = beg;
    for (; j + 2 <= end; j += 2) {
        int2 e0 = g_es2[j], e1 = g_es2[j + 1];
        float as0 = g_asrc1[e0.x * HEADS + h];
        float as1 = g_asrc1[e1.x * HEADS + h];
        uint2 p0 = *(const uint2*)(g_xl1h + (long)e0.x * F1 + l * 4);
        uint2 p1 = *(const uint2*)(g_xl1h + (long)e1.x * F1 + l * 4);
        float al0 = as0 + adst + __int_as_float(e0.y) * cf;
        float al1 = as1 + adst + __int_as_float(e1.y) * cf;
        al0 = fmaxf(al0, 0.2f * al0);
        al1 = fmaxf(al1, 0.2f * al1);
        float ex0, ex1;
        EX2(ex0, al0); EX2(ex1, al1);
        den += ex0 + ex1;
        float2 a0 = __half22float2(*reinterpret_cast<__half2*>(&p0.x));
        float2 b0 = __half22float2(*reinterpret_cast<__half2*>(&p0.y));
        float2 a1 = __half22float2(*reinterpret_cast<__half2*>(&p1.x));
        float2 b1 = __half22float2(*reinterpret_cast<__half2*>(&p1.y));
        acc.x += ex0 * a0.x + ex1 * a1.x;
        acc.y += ex0 * a0.y + ex1 * a1.y;
        acc.z += ex0 * b0.x + ex1 * b1.x;
        acc.w += ex0 * b0.y + ex1 * b1.y;
    }
    if (j < end) {
        int2 e0 = g_es2[j];
        float as0 = g_asrc1[e0.x * HEADS + h];
        uint2 p0 = *(const uint2*)(g_xl1h + (long)e0.x * F1 + l * 4);
        float al0 = as0 + adst + __int_as_float(e0.y) * cf;
        al0 = fmaxf(al0, 0.2f * al0);
        float ex0; EX2(ex0, al0);
        den += ex0;
        float2 a0 = __half22float2(*reinterpret_cast<__half2*>(&p0.x));
        float2 b0 = __half22float2(*reinterpret_cast<__half2*>(&p0.y));
        acc.x += ex0 * a0.x; acc.y += ex0 * a0.y;
        acc.z += ex0 * b0.x; acc.w += ex0 * b0.y;
    }
    float inv = 1.f / den;
    float4 b = *(const float4*)&bias1[l * 4];
    float4 v;
    v.x = acc.x * inv + b.x; v.y = acc.y * inv + b.y;
    v.z = acc.z * inv + b.z; v.w = acc.w * inv + b.w;
    v.x = v.x > 0.f ? v.x : expm1f(v.x);
    v.y = v.y > 0.f ? v.y : expm1f(v.y);
    v.z = v.z > 0.f ? v.z : expm1f(v.z);
    v.w = v.w > 0.f ? v.w : expm1f(v.w);

    __half2 h01 = __floats2half2_rn(v.x, v.y);
    __half2 h23 = __floats2half2_rn(v.z, v.w);
    uint2 st;
    st.x = *reinterpret_cast<unsigned*>(&h01);
    st.y = *reinterpret_cast<unsigned*>(&h23);
    *(uint2*)(g_h1h + (long)d * F1 + l * 4) = st;
}

// ---------------------------------------------------------------------------
// xl2 = h @ W2 (128x32): register-tiled GEMM, 32 nodes/block, 128 threads.
// CONFLICT-FREE staging: warp w owns k in [32w,32w+32), lane = node index;
// STS addresses sxT[k*36+lane] span all 32 banks. Fused att2 dots (log2e).
__global__ void __launch_bounds__(128) k_lin2(
    const float* __restrict__ w2, const float* __restrict__ a2s,
    const float* __restrict__ a2d) {
    __shared__ float sxT[FIN * 36];   // [k][node(+pad)] of h
    int t = threadIdx.x;
    int lane = t & 31, wid = t >> 5;
    int nbase = blockIdx.x * 32;

    {
        int n = min(nbase + lane, NN - 1);
        const uint4* src = (const uint4*)(g_h1h + (long)n * F1 + wid * 32);
        #pragma unroll
        for (int q = 0; q < 4; q++) {
            uint4 u = src[q];   // 8 halves: k = wid*32 + q*8 .. +7
            int k0 = wid * 32 + q * 8;
            float2 f;
            f = __half22float2(*reinterpret_cast<__half2*>(&u.x));
            sxT[(k0 + 0) * 36 + lane] = f.x; sxT[(k0 + 1) * 36 + lane] = f.y;
            f = __half22float2(*reinterpret_cast<__half2*>(&u.y));
            sxT[(k0 + 2) * 36 + lane] = f.x; sxT[(k0 + 3) * 36 + lane] = f.y;
            f = __half22float2(*reinterpret_cast<__half2*>(&u.z));
            sxT[(k0 + 4) * 36 + lane] = f.x; sxT[(k0 + 5) * 36 + lane] = f.y;
            f = __half22float2(*reinterpret_cast<__half2*>(&u.w));
            sxT[(k0 + 6) * 36 + lane] = f.x; sxT[(k0 + 7) * 36 + lane] = f.y;
        }
    }
    __syncthreads();

    const int col = lane;
    const int jg = wid;           // node group: nodes jg*8..jg*8+7
    unsigned long long acc2[4];
    #pragma unroll
    for (int p = 0; p < 4; p++) acc2[p] = 0ull;
    #pragma unroll 4
    for (int k = 0; k < FIN; k++) {
        float wv = w2[k * OUTC + col];
        unsigned long long wv2;
        asm("mov.b64 %0, {%1, %1};" : "=l"(wv2) : "f"(wv));
        ulonglong2 xv0 = *(const ulonglong2*)&sxT[k * 36 + jg * 8];
        ulonglong2 xv1 = *(const ulonglong2*)&sxT[k * 36 + jg * 8 + 4];
        FMA2(acc2[0], xv0.x, wv2);
        FMA2(acc2[1], xv0.y, wv2);
        FMA2(acc2[2], xv1.x, wv2);
        FMA2(acc2[3], xv1.y, wv2);
    }

    float sA = a2s[col] * LOG2E, sD = a2d[col] * LOG2E;
    #pragma unroll
    for (int p = 0; p < 4; p++) {
        float lo, hi;
        asm("mov.b64 {%0, %1}, %2;" : "=f"(lo), "=f"(hi) : "l"(acc2[p]));
        int n0 = nbase + jg * 8 + p * 2;
        if (n0 < NN)     g_xl2[n0 * OUTC + col]       = lo;
        if (n0 + 1 < NN) g_xl2[(n0 + 1) * OUTC + col] = hi;
        float vs0 = lo * sA, vd0 = lo * sD, vs1 = hi * sA, vd1 = hi * sD;
        #pragma unroll
        for (int o = 16; o; o >>= 1) {
            vs0 += __shfl_xor_sync(0xffffffffu, vs0, o);
            vd0 += __shfl_xor_sync(0xffffffffu, vd0, o);
            vs1 += __shfl_xor_sync(0xffffffffu, vs1, o);
            vd1 += __shfl_xor_sync(0xffffffffu, vd1, o);
        }
        if (lane == 0 && n0 < NN) {
            g_asrc2[n0] = vs0;
            g_adst2[n0] = vd0;
            if (n0 + 1 < NN) { g_asrc2[n0 + 1] = vs1; g_adst2[n0 + 1] = vd1; }
        }
    }
}

// ---------------------------------------------------------------------------
// Gather edge pass layer2 (proven x2 loop, exp2). 512 threads.
__global__ void __launch_bounds__(512) k_edge2g(float* __restrict__ out,
                                                const float* __restrict__ bias2) {
    int d = blockIdx.x * 16 + (threadIdx.x >> 5);
    if (d >= NN) return;
    int l = threadIdx.x & 31;
    int beg = d * CAP;
    int end = beg + min(g_cnt[d], CAP);
    float adst = g_adst2[d];
    float cf = g_coef2;
    float acc = 0.f, den = 0.f;
    int j = beg;
    for (; j + 2 <= end; j += 2) {
        int2 e0 = g_es2[j], e1 = g_es2[j + 1];
        float as0 = g_asrc2[e0.x];
        float as1 = g_asrc2[e1.x];
        float v0 = g_xl2[e0.x * OUTC + l];
        float v1 = g_xl2[e1.x * OUTC + l];
        float al0 = as0 + adst + __int_as_float(e0.y) * cf;
        float al1 = as1 + adst + __int_as_float(e1.y) * cf;
        al0 = fmaxf(al0, 0.2f * al0);
        al1 = fmaxf(al1, 0.2f * al1);
        float ex0, ex1;
        EX2(ex0, al0); EX2(ex1, al1);
        den += ex0 + ex1;
        acc += ex0 * v0 + ex1 * v1;
    }
    if (j < end) {
        int2 e0 = g_es2[j];
        float al0 = g_asrc2[e0.x] + adst + __int_as_float(e0.y) * cf;
        al0 = fmaxf(al0, 0.2f * al0);
        float ex0; EX2(ex0, al0);
        den += ex0;
        acc += ex0 * g_xl2[e0.x * OUTC + l];
    }
    out[(long)d * OUTC + l] = acc / den + bias2[l];
}

// ---------------------------------------------------------------------------
extern "C" void kernel_launch(void* const* d_in, const int* in_sizes, int n_in,
                              void* d_out, int out_size) {
    const float* x        = (const float*)d_in[0];
    const int*   eidx     = (const int*)  d_in[1];
    const float* eattr    = (const float*)d_in[2];
    const float* lin1_w   = (const float*)d_in[3];
    const float* att1_src = (const float*)d_in[4];
    const float* att1_dst = (const float*)d_in[5];
    const float* lin1_ew  = (const float*)d_in[6];
    const float* att1_e   = (const float*)d_in[7];
    const float* bias1    = (const float*)d_in[8];
    const float* lin2_w   = (const float*)d_in[9];
    const float* att2_src = (const float*)d_in[10];
    const float* att2_dst = (const float*)d_in[11];
    const float* lin2_ew  = (const float*)d_in[12];
    const float* att2_e   = (const float*)d_in[13];
    const float* bias2    = (const float*)d_in[14];
    float* out = (float*)d_out;

    static cudaStream_t sB = nullptr;
    static cudaEvent_t evFork = nullptr, evB = nullptr;
    static bool streamsOk = false;
    if (sB == nullptr && !streamsOk) {
        bool ok = (cudaStreamCreateWithFlags(&sB, cudaStreamNonBlocking) == cudaSuccess)
               && (cudaEventCreateWithFlags(&evFork, cudaEventDisableTiming) == cudaSuccess)
               && (cudaEventCreateWithFlags(&evB, cudaEventDisableTiming) == cudaSuccess);
        streamsOk = ok;
        if (!ok) sB = nullptr;
    }

    if (streamsOk) {
        // idx0: lin1 on side stream (independent of edge bucketing)
        cudaEventRecord(evFork, 0);
        cudaStreamWaitEvent(sB, evFork, 0);
        k_lin1<<<(NN + 31) / 32, 128, 0, sB>>>(x, lin1_w, att1_src, att1_dst);
        cudaEventRecord(evB, sB);

        // idx1: prep, idx2: scatter
        k_prep<<<512, 256>>>(eattr, lin1_ew, att1_e, lin2_ew, att2_e);
        k_scatter<<<(ETOT / 4 + 255) / 256, 256>>>(eidx, eattr);

        // idx3: edge1 (ncu -s5 profiles this), idx4: lin2, idx5: edge2g
        cudaStreamWaitEvent(0, evB, 0);
        k_edge1<<<(NN + 15) / 16, 512>>>(bias1);
        k_lin2<<<(NN + 31) / 32, 128>>>(lin2_w, att2_src, att2_dst);
        k_edge2g<<<(NN + 15) / 16, 512>>>(out, bias2);
    } else {
        // serial fallback
        k_lin1<<<(NN + 31) / 32, 128>>>(x, lin1_w, att1_src, att1_dst);
        k_prep<<<512, 256>>>(eattr, lin1_ew, att1_e, lin2_ew, att2_e);
        k_scatter<<<(ETOT / 4 + 255) / 256, 256>>>(eidx, eattr);
        k_edge1<<<(NN + 15) / 16, 512>>>(bias1);
        k_lin2<<<(NN + 31) / 32, 128>>>(lin2_w, att2_src, att2_dst);
        k_edge2g<<<(NN + 15) / 16, 512>>>(out, bias2);
    }
}